// round 1
// baseline (speedup 1.0000x reference)
#include <cuda_runtime.h>

#define NN   50000
#define EE   400000
#define NH   12
#define HC   32
#define D0   128
#define NHC  (NH*HC)   // 384
#define NC   2

// ---------------- scratch (static device globals; no runtime allocation) ---------
__device__ float g_xl[(size_t)NN * NHC];       // 76.8 MB
__device__ float g_xr[(size_t)NN * NHC];       // 76.8 MB
__device__ float g_act[(size_t)NN * HC];       // layer activations
__device__ float g_logits[(size_t)EE * NH];    // 19.2 MB
__device__ float g_xlo[NN * NC];
__device__ float g_xro[NN * NC];
__device__ float g_elog[EE];
__device__ int   g_rowptr[NN + 1];
__device__ int   g_cnt[NN];
__device__ int   g_eid[EE];

__device__ __forceinline__ float lrelu(float v) { return v > 0.f ? v : 0.2f * v; }

// ---------------- CSR build --------------------------------------------------
__global__ void k_zero_int(int* p, int n) {
    int i = blockIdx.x * blockDim.x + threadIdx.x;
    if (i < n) p[i] = 0;
}

__global__ void k_count(const int* __restrict__ dst, int* cnt) {
    int i = blockIdx.x * blockDim.x + threadIdx.x;
    if (i < EE) atomicAdd(&cnt[dst[i]], 1);
}

// single-block exclusive scan over NN counts (49 chunks of 1024)
__global__ void k_scan(const int* __restrict__ cnt, int* rowptr) {
    __shared__ int tmp[1024];
    __shared__ int carry;
    if (threadIdx.x == 0) { carry = 0; rowptr[0] = 0; }
    __syncthreads();
    for (int base = 0; base < NN; base += 1024) {
        int i = base + threadIdx.x;
        int v = (i < NN) ? cnt[i] : 0;
        tmp[threadIdx.x] = v;
        __syncthreads();
        for (int off = 1; off < 1024; off <<= 1) {
            int t = (threadIdx.x >= off) ? tmp[threadIdx.x - off] : 0;
            __syncthreads();
            tmp[threadIdx.x] += t;
            __syncthreads();
        }
        if (i < NN) rowptr[i + 1] = carry + tmp[threadIdx.x];
        __syncthreads();
        if (threadIdx.x == 0) carry += tmp[1023];
        __syncthreads();
    }
}

__global__ void k_scatter(const int* __restrict__ dst, const int* __restrict__ rowptr,
                          int* cnt, int* eid) {
    int i = blockIdx.x * blockDim.x + threadIdx.x;
    if (i < EE) {
        int d = dst[i];
        int pos = rowptr[d] + atomicAdd(&cnt[d], 1);
        eid[pos] = i;
    }
}

// ---------------- fp32 SGEMM: C[M,Ncol] = A[M,K] @ W[K,Ncol] + bias ----------
template <int BM, int BN, int BK, int TM, int TN>
__global__ void k_sgemm(const float* __restrict__ A, const float* __restrict__ W,
                        const float* __restrict__ bias, float* __restrict__ C,
                        int M, int K, int Ncol) {
    static_assert((BM / TM) * (BN / TN) == 256, "256 threads");
    __shared__ float As[BK][BM];   // transposed A tile
    __shared__ float Bs[BK][BN];
    const int tid  = threadIdx.x;
    const int tcol = tid % (BN / TN);
    const int trow = tid / (BN / TN);
    const int rowBase = blockIdx.y * BM;
    const int colBase = blockIdx.x * BN;

    float acc[TM][TN];
#pragma unroll
    for (int i = 0; i < TM; i++)
#pragma unroll
        for (int j = 0; j < TN; j++) acc[i][j] = 0.f;

    for (int k0 = 0; k0 < K; k0 += BK) {
        for (int t = tid; t < BM * BK; t += 256) {
            int r = t / BK, c = t % BK;
            int gr = rowBase + r;
            As[c][r] = (gr < M) ? A[(size_t)gr * K + k0 + c] : 0.f;
        }
        for (int t = tid; t < BK * BN; t += 256) {
            int r = t / BN, c = t % BN;
            Bs[r][c] = W[(size_t)(k0 + r) * Ncol + colBase + c];
        }
        __syncthreads();
#pragma unroll
        for (int kk = 0; kk < BK; kk++) {
            float a[TM], b[TN];
#pragma unroll
            for (int i = 0; i < TM; i++) a[i] = As[kk][trow * TM + i];
#pragma unroll
            for (int j = 0; j < TN; j++) b[j] = Bs[kk][tcol * TN + j];
#pragma unroll
            for (int i = 0; i < TM; i++)
#pragma unroll
                for (int j = 0; j < TN; j++) acc[i][j] += a[i] * b[j];
        }
        __syncthreads();
    }
#pragma unroll
    for (int i = 0; i < TM; i++) {
        int gr = rowBase + trow * TM + i;
        if (gr < M) {
#pragma unroll
            for (int j = 0; j < TN; j++) {
                int gc = colBase + tcol * TN + j;
                C[(size_t)gr * Ncol + gc] = acc[i][j] + bias[gc];
            }
        }
    }
}

// ---------------- per-edge logits (12 heads): warp per edge -------------------
__global__ void k_edge_logits(const int* __restrict__ src, const int* __restrict__ dst,
                              const float* __restrict__ att) {
    int e    = (blockIdx.x * blockDim.x + threadIdx.x) >> 5;
    int lane = threadIdx.x & 31;
    if (e >= EE) return;
    int s = src[e], d = dst[e];
    const float* xls = g_xl + (size_t)s * NHC;
    const float* xrd = g_xr + (size_t)d * NHC;
#pragma unroll
    for (int h = 0; h < NH; h++) {
        float v = lrelu(xls[h * HC + lane] + xrd[h * HC + lane]) * att[h * HC + lane];
#pragma unroll
        for (int o = 16; o; o >>= 1) v += __shfl_xor_sync(0xffffffffu, v, o);
        if (lane == 0) g_logits[(size_t)e * NH + h] = v;
    }
}

// ---------------- aggregate (12 heads, 32 ch): warp per node ------------------
// segment softmax (incl. self-loop) + weighted sum of xl[src], mean-over-heads,
// +bias, ELU. No float atomics (CSR ordering).
__global__ void k_aggregate(const float* __restrict__ att, const float* __restrict__ bias,
                            const int* __restrict__ src) {
    int node = (blockIdx.x * blockDim.x + threadIdx.x) >> 5;
    int lane = threadIdx.x & 31;
    int wib  = threadIdx.x >> 5;
    __shared__ float s_m[8][NH];
    if (node >= NN) return;

    const float* xli = g_xl + (size_t)node * NHC;
    const float* xri = g_xr + (size_t)node * NHC;

    // self-loop logit per head (all lanes end with the value)
    float sl[NH];
#pragma unroll
    for (int h = 0; h < NH; h++) {
        float v = lrelu(xli[h * HC + lane] + xri[h * HC + lane]) * att[h * HC + lane];
#pragma unroll
        for (int o = 16; o; o >>= 1) v += __shfl_xor_sync(0xffffffffu, v, o);
        sl[h] = v;
    }

    const int start = g_rowptr[node], end = g_rowptr[node + 1];

    // pass A: per-head max over incoming edges (lane-strided) + self
    float m[NH];
#pragma unroll
    for (int h = 0; h < NH; h++) m[h] = sl[h];
    for (int p = start + lane; p < end; p += 32) {
        const float* lg = g_logits + (size_t)g_eid[p] * NH;
#pragma unroll
        for (int h = 0; h < NH; h++) m[h] = fmaxf(m[h], lg[h]);
    }
#pragma unroll
    for (int o = 16; o; o >>= 1)
#pragma unroll
        for (int h = 0; h < NH; h++) m[h] = fmaxf(m[h], __shfl_xor_sync(0xffffffffu, m[h], o));

    if (lane == 0) {
#pragma unroll
        for (int h = 0; h < NH; h++) s_m[wib][h] = m[h];
    }
    __syncwarp();

    // pass B (fused denom + weighted accumulation):
    // lane h (<12) computes w_e = exp(logit_e[h]-m[h]) and its running sum;
    // all lanes accumulate acc[h] += w_e * xl[src][h, lane] via shfl broadcast.
    float wself[NH], acc[NH];
#pragma unroll
    for (int h = 0; h < NH; h++) {
        wself[h] = __expf(sl[h] - m[h]);
        acc[h]   = wself[h] * xli[h * HC + lane];
    }
    float my_m = (lane < NH) ? s_m[wib][lane] : 0.f;
    float dw = 0.f;
    for (int p = start; p < end; p++) {
        int e = g_eid[p];
        float wv = 0.f;
        if (lane < NH) wv = __expf(g_logits[(size_t)e * NH + lane] - my_m);
        dw += wv;
        const float* xs = g_xl + (size_t)src[e] * NHC;
#pragma unroll
        for (int h = 0; h < NH; h++)
            acc[h] += __shfl_sync(0xffffffffu, wv, h) * xs[h * HC + lane];
    }

    float o = 0.f;
#pragma unroll
    for (int h = 0; h < NH; h++) {
        float denom = __shfl_sync(0xffffffffu, dw, h) + wself[h];
        o += acc[h] / (denom + 1e-16f);
    }
    o = o * (1.f / 12.f) + bias[lane];
    o = (o > 0.f) ? o : (__expf(o) - 1.f);   // ELU
    g_act[(size_t)node * HC + lane] = o;
}

// ---------------- output GATv2 layer (heads=1, C=2) ---------------------------
__global__ void k_lin_out(const float* __restrict__ Wl, const float* __restrict__ bl,
                          const float* __restrict__ Wr, const float* __restrict__ br) {
    int node = (blockIdx.x * blockDim.x + threadIdx.x) >> 5;
    int lane = threadIdx.x & 31;
    if (node >= NN) return;
    float hv = g_act[(size_t)node * HC + lane];
#pragma unroll
    for (int j = 0; j < NC; j++) {
        float a = hv * Wl[lane * NC + j];
        float b = hv * Wr[lane * NC + j];
#pragma unroll
        for (int o = 16; o; o >>= 1) {
            a += __shfl_xor_sync(0xffffffffu, a, o);
            b += __shfl_xor_sync(0xffffffffu, b, o);
        }
        if (lane == 0) {
            g_xlo[node * NC + j] = a + bl[j];
            g_xro[node * NC + j] = b + br[j];
        }
    }
}

__global__ void k_edge_logit_out(const int* __restrict__ src, const int* __restrict__ dst,
                                 const float* __restrict__ att) {
    int i = blockIdx.x * blockDim.x + threadIdx.x;
    if (i >= EE) return;
    int s = src[i], d = dst[i];
    float l = att[0] * lrelu(g_xlo[s * NC]     + g_xro[d * NC]) +
              att[1] * lrelu(g_xlo[s * NC + 1] + g_xro[d * NC + 1]);
    g_elog[i] = l;
}

__global__ void k_aggregate_out(const int* __restrict__ src, const float* __restrict__ att,
                                const float* __restrict__ bias, float* __restrict__ out) {
    int node = (blockIdx.x * blockDim.x + threadIdx.x) >> 5;
    int lane = threadIdx.x & 31;
    if (node >= NN) return;
    float x0 = g_xlo[node * NC], x1 = g_xlo[node * NC + 1];
    float r0 = g_xro[node * NC], r1 = g_xro[node * NC + 1];
    float sl = att[0] * lrelu(x0 + r0) + att[1] * lrelu(x1 + r1);
    const int start = g_rowptr[node], end = g_rowptr[node + 1];

    float m = sl;
    for (int p = start + lane; p < end; p += 32) m = fmaxf(m, g_elog[g_eid[p]]);
#pragma unroll
    for (int o = 16; o; o >>= 1) m = fmaxf(m, __shfl_xor_sync(0xffffffffu, m, o));

    float dsum = 0.f, a0 = 0.f, a1 = 0.f;
    for (int p = start + lane; p < end; p += 32) {
        int e = g_eid[p];
        int s = src[e];
        float w = __expf(g_elog[e] - m);
        dsum += w;
        a0 += w * g_xlo[s * NC];
        a1 += w * g_xlo[s * NC + 1];
    }
#pragma unroll
    for (int o = 16; o; o >>= 1) {
        dsum += __shfl_xor_sync(0xffffffffu, dsum, o);
        a0   += __shfl_xor_sync(0xffffffffu, a0, o);
        a1   += __shfl_xor_sync(0xffffffffu, a1, o);
    }
    float ws = __expf(sl - m);
    dsum += ws; a0 += ws * x0; a1 += ws * x1;
    float dinv = 1.f / (dsum + 1e-16f);
    if (lane == 0) {
        out[node * NC]     = a0 * dinv + bias[0];
        out[node * NC + 1] = a1 * dinv + bias[1];
    }
}

// ---------------- launch ------------------------------------------------------
extern "C" void kernel_launch(void* const* d_in, const int* in_sizes, int n_in,
                              void* d_out, int out_size) {
    const float* x     = (const float*)d_in[0];
    const int*   ei    = (const int*)d_in[1];
    const float* Wl0   = (const float*)d_in[2];
    const float* bl0   = (const float*)d_in[3];
    const float* Wr0   = (const float*)d_in[4];
    const float* br0   = (const float*)d_in[5];
    const float* att0  = (const float*)d_in[6];
    const float* bias0 = (const float*)d_in[7];
    const float* Wl1   = (const float*)d_in[8];
    const float* bl1   = (const float*)d_in[9];
    const float* Wr1   = (const float*)d_in[10];
    const float* br1   = (const float*)d_in[11];
    const float* att1  = (const float*)d_in[12];
    const float* bias1 = (const float*)d_in[13];
    const float* Wlo   = (const float*)d_in[14];
    const float* blo   = (const float*)d_in[15];
    const float* Wro   = (const float*)d_in[16];
    const float* bro   = (const float*)d_in[17];
    const float* atto  = (const float*)d_in[18];
    const float* biaso = (const float*)d_in[19];
    float* out = (float*)d_out;

    const int* src = ei;        // edge_index[0]
    const int* dst = ei + EE;   // edge_index[1]

    float *pxl, *pxr, *pact;
    int *pcnt, *prow, *peid;
    cudaGetSymbolAddress((void**)&pxl,  g_xl);
    cudaGetSymbolAddress((void**)&pxr,  g_xr);
    cudaGetSymbolAddress((void**)&pact, g_act);
    cudaGetSymbolAddress((void**)&pcnt, g_cnt);
    cudaGetSymbolAddress((void**)&prow, g_rowptr);
    cudaGetSymbolAddress((void**)&peid, g_eid);

    // CSR by destination (edge topology is an input, rebuilt every call)
    k_zero_int<<<(NN + 255) / 256, 256>>>(pcnt, NN);
    k_count  <<<(EE + 255) / 256, 256>>>(dst, pcnt);
    k_scan   <<<1, 1024>>>(pcnt, prow);
    k_zero_int<<<(NN + 255) / 256, 256>>>(pcnt, NN);
    k_scatter<<<(EE + 255) / 256, 256>>>(dst, prow, pcnt, peid);

    dim3 g0(NHC / 64, (NN + 127) / 128);

    // layer 0
    k_sgemm<128, 64, 16, 8, 4><<<g0, 256>>>(x, Wl0, bl0, pxl, NN, D0, NHC);
    k_sgemm<128, 64, 16, 8, 4><<<g0, 256>>>(x, Wr0, br0, pxr, NN, D0, NHC);
    k_edge_logits<<<(EE + 7) / 8, 256>>>(src, dst, att0);
    k_aggregate  <<<(NN + 7) / 8, 256>>>(att0, bias0, src);

    // layer 1
    k_sgemm<128, 64, 16, 8, 4><<<g0, 256>>>(pact, Wl1, bl1, pxl, NN, HC, NHC);
    k_sgemm<128, 64, 16, 8, 4><<<g0, 256>>>(pact, Wr1, br1, pxr, NN, HC, NHC);
    k_edge_logits<<<(EE + 7) / 8, 256>>>(src, dst, att1);
    k_aggregate  <<<(NN + 7) / 8, 256>>>(att1, bias1, src);

    // output layer (heads=1, C=2)
    k_lin_out       <<<(NN + 7) / 8, 256>>>(Wlo, blo, Wro, bro);
    k_edge_logit_out<<<(EE + 255) / 256, 256>>>(src, dst, atto);
    k_aggregate_out <<<(NN + 7) / 8, 256>>>(src, atto, biaso, out);
}

// round 2
// speedup vs baseline: 1.2579x; 1.2579x over previous
#include <cuda_runtime.h>

#define NN   50000
#define EE   400000
#define NH   12
#define HC   32
#define D0   128
#define NHC  (NH*HC)   // 384
#define NC   2

// ---------------- scratch (static device globals) -----------------------------
__device__ float g_xl[(size_t)NN * NHC];       // 76.8 MB
__device__ float g_xr[(size_t)NN * NHC];       // 76.8 MB
__device__ float g_act[(size_t)NN * HC];
__device__ float g_xlo[NN * NC];
__device__ float g_xro[NN * NC];
__device__ int   g_rowptr[NN + 1];
__device__ int   g_cnt[NN];
__device__ int   g_adj[EE];                    // src node ids grouped by dst

__device__ __forceinline__ float lrelu(float v) { return v > 0.f ? v : 0.2f * v; }

__device__ __forceinline__ void ffma2(unsigned long long& d, unsigned long long a,
                                      unsigned long long b) {
    asm("fma.rn.f32x2 %0, %1, %2, %0;" : "+l"(d) : "l"(a), "l"(b));
}
__device__ __forceinline__ unsigned long long dup2(float v) {
    unsigned long long r;
    asm("mov.b64 %0, {%1, %1};" : "=l"(r) : "f"(v));
    return r;
}

// ---------------- CSR build ----------------------------------------------------
__global__ void k_zero_int(int* p, int n) {
    int i = blockIdx.x * blockDim.x + threadIdx.x;
    if (i < n) p[i] = 0;
}

__global__ void k_count(const int* __restrict__ dst, int* cnt) {
    int i = blockIdx.x * blockDim.x + threadIdx.x;
    if (i < EE) atomicAdd(&cnt[dst[i]], 1);
}

// single-block warp-scan prefix sum over NN counts
__global__ void k_scan(const int* __restrict__ cnt, int* __restrict__ rowptr) {
    __shared__ int wsum[32];
    __shared__ int carry;
    int lane = threadIdx.x & 31, wid = threadIdx.x >> 5;
    if (threadIdx.x == 0) { carry = 0; rowptr[0] = 0; }
    __syncthreads();
    for (int base = 0; base < NN; base += 1024) {
        int i = base + threadIdx.x;
        int v = (i < NN) ? cnt[i] : 0;
        int x = v;
#pragma unroll
        for (int o = 1; o < 32; o <<= 1) {
            int t = __shfl_up_sync(0xffffffffu, x, o);
            if (lane >= o) x += t;
        }
        if (lane == 31) wsum[wid] = x;
        __syncthreads();
        if (wid == 0) {
            int s = wsum[lane];
#pragma unroll
            for (int o = 1; o < 32; o <<= 1) {
                int t = __shfl_up_sync(0xffffffffu, s, o);
                if (lane >= o) s += t;
            }
            wsum[lane] = s;
        }
        __syncthreads();
        int incl = x + (wid ? wsum[wid - 1] : 0) + carry;
        if (i < NN) rowptr[i + 1] = incl;
        int total = wsum[31];
        __syncthreads();
        if (threadIdx.x == 0) carry += total;
        __syncthreads();
    }
}

// scatter src ids grouped by dst (consumes cnt back down to zero)
__global__ void k_scatter(const int* __restrict__ dst, const int* __restrict__ src,
                          const int* __restrict__ rowptr, int* cnt, int* adj) {
    int i = blockIdx.x * blockDim.x + threadIdx.x;
    if (i < EE) {
        int d = dst[i];
        int pos = rowptr[d] + (atomicAdd(&cnt[d], -1) - 1);
        adj[pos] = src[i];
    }
}

// ---------------- f32x2 SGEMM: C = A[M,K] @ W[K,Ncol] + bias -------------------
// BM=128, BN=128, BK=16; 256 threads; per-thread 8x8 via packed-pair FFMA2.
// blockIdx.z selects (Wa->Ca) vs (Wb->Cb), sharing nothing but code (overlap).
template <int BM, int BN, int BK, int TM, int TN>
__global__ __launch_bounds__(256)
void k_sgemm2(const float* __restrict__ A,
              const float* __restrict__ Wa, const float* __restrict__ ba, float* __restrict__ Ca,
              const float* __restrict__ Wb, const float* __restrict__ bb_, float* __restrict__ Cb,
              int M, int K, int Ncol) {
    const float* W    = blockIdx.z ? Wb  : Wa;
    const float* bias = blockIdx.z ? bb_ : ba;
    float*       C    = blockIdx.z ? Cb  : Ca;

    __shared__ float As[BK][BM + 2];   // +2 pad: conflict-free transpose stores, 8B-aligned rows
    __shared__ float Bs[BK][BN];

    const int tid  = threadIdx.x;
    const int tcol = tid & 15;         // 16 cols of threads
    const int trow = tid >> 4;         // 16 rows of threads
    const int rowBase = blockIdx.y * BM;
    const int colBase = blockIdx.x * BN;

    unsigned long long acc[TM / 2][TN];
#pragma unroll
    for (int i = 0; i < TM / 2; i++)
#pragma unroll
        for (int j = 0; j < TN; j++) acc[i][j] = 0ull;

    for (int k0 = 0; k0 < K; k0 += BK) {
        // load A tile (float4 along K), store transposed
#pragma unroll
        for (int t = tid; t < BM * BK / 4; t += 256) {
            int r  = t >> 2;            // 0..127
            int c4 = (t & 3) * 4;       // 0,4,8,12
            int gr = rowBase + r;
            float4 v = make_float4(0.f, 0.f, 0.f, 0.f);
            if (gr < M) v = *reinterpret_cast<const float4*>(&A[(size_t)gr * K + k0 + c4]);
            As[c4 + 0][r] = v.x;
            As[c4 + 1][r] = v.y;
            As[c4 + 2][r] = v.z;
            As[c4 + 3][r] = v.w;
        }
        // load B tile (float4, coalesced)
#pragma unroll
        for (int t = tid; t < BK * BN / 4; t += 256) {
            int r  = t / (BN / 4);
            int c4 = (t % (BN / 4)) * 4;
            *reinterpret_cast<float4*>(&Bs[r][c4]) =
                *reinterpret_cast<const float4*>(&W[(size_t)(k0 + r) * Ncol + colBase + c4]);
        }
        __syncthreads();
#pragma unroll
        for (int kk = 0; kk < BK; kk++) {
            const unsigned long long* ap =
                reinterpret_cast<const unsigned long long*>(&As[kk][trow * TM]);
            unsigned long long a2[TM / 2];
#pragma unroll
            for (int i = 0; i < TM / 2; i++) a2[i] = ap[i];
            float4 b0 = *reinterpret_cast<const float4*>(&Bs[kk][tcol * TN]);
            float4 b1 = *reinterpret_cast<const float4*>(&Bs[kk][tcol * TN + 4]);
            float bj[TN] = {b0.x, b0.y, b0.z, b0.w, b1.x, b1.y, b1.z, b1.w};
#pragma unroll
            for (int j = 0; j < TN; j++) {
                unsigned long long bb = dup2(bj[j]);
#pragma unroll
                for (int i = 0; i < TM / 2; i++) ffma2(acc[i][j], a2[i], bb);
            }
        }
        __syncthreads();
    }

    float bv[TN];
#pragma unroll
    for (int j = 0; j < TN; j++) bv[j] = bias[colBase + tcol * TN + j];
#pragma unroll
    for (int i = 0; i < TM / 2; i++) {
        int gr0 = rowBase + trow * TM + 2 * i;
        if (gr0 < M) {
#pragma unroll
            for (int j = 0; j < TN; j++) {
                float2 f = *reinterpret_cast<float2*>(&acc[i][j]);
                int gc = colBase + tcol * TN + j;
                C[(size_t)gr0 * Ncol + gc] = f.x + bv[j];
                if (gr0 + 1 < M) C[(size_t)(gr0 + 1) * Ncol + gc] = f.y + bv[j];
            }
        }
    }
}

// ---------------- fused GATv2 layer: logits + online softmax + aggregate ------
// warp per dst node; single gather of xl[src] per edge; ELU + mean-over-heads.
__global__ __launch_bounds__(256)
void k_aggregate(const float* __restrict__ att, const float* __restrict__ bias) {
    int node = (blockIdx.x * blockDim.x + threadIdx.x) >> 5;
    int lane = threadIdx.x & 31;
    if (node >= NN) return;

    const float* xli = g_xl + (size_t)node * NHC;
    const float* xri = g_xr + (size_t)node * NHC;

    float attv[NH], xrv[NH], m[NH], d[NH], acc[NH];
#pragma unroll
    for (int h = 0; h < NH; h++) {
        attv[h] = att[h * HC + lane];
        xrv[h]  = xri[h * HC + lane];
    }
    // self-loop initializes the online state
#pragma unroll
    for (int h = 0; h < NH; h++) {
        float xv = xli[h * HC + lane];
        float t  = lrelu(xv + xrv[h]) * attv[h];
#pragma unroll
        for (int o = 16; o; o >>= 1) t += __shfl_xor_sync(0xffffffffu, t, o);
        m[h] = t; d[h] = 1.f; acc[h] = xv;
    }

    const int start = g_rowptr[node], end = g_rowptr[node + 1];
    for (int p = start; p < end; ++p) {
        int s = g_adj[p];
        const float* xs = g_xl + (size_t)s * NHC;
#pragma unroll
        for (int h = 0; h < NH; h++) {
            float xv = xs[h * HC + lane];
            float t  = lrelu(xv + xrv[h]) * attv[h];
#pragma unroll
            for (int o = 16; o; o >>= 1) t += __shfl_xor_sync(0xffffffffu, t, o);
            float mn = fmaxf(m[h], t);
            float sc = __expf(m[h] - mn);
            float w  = __expf(t - mn);
            d[h]   = d[h] * sc + w;
            acc[h] = acc[h] * sc + w * xv;
            m[h]   = mn;
        }
    }

    float o = 0.f;
#pragma unroll
    for (int h = 0; h < NH; h++) o += acc[h] / d[h];
    o = o * (1.f / NH) + bias[lane];
    o = (o > 0.f) ? o : (__expf(o) - 1.f);   // ELU
    g_act[(size_t)node * HC + lane] = o;
}

// ---------------- output GATv2 layer (heads=1, C=2) ----------------------------
__global__ void k_lin_out(const float* __restrict__ Wl, const float* __restrict__ bl,
                          const float* __restrict__ Wr, const float* __restrict__ br) {
    int node = (blockIdx.x * blockDim.x + threadIdx.x) >> 5;
    int lane = threadIdx.x & 31;
    if (node >= NN) return;
    float hv = g_act[(size_t)node * HC + lane];
#pragma unroll
    for (int j = 0; j < NC; j++) {
        float a = hv * Wl[lane * NC + j];
        float b = hv * Wr[lane * NC + j];
#pragma unroll
        for (int o = 16; o; o >>= 1) {
            a += __shfl_xor_sync(0xffffffffu, a, o);
            b += __shfl_xor_sync(0xffffffffu, b, o);
        }
        if (lane == 0) {
            g_xlo[node * NC + j] = a + bl[j];
            g_xro[node * NC + j] = b + br[j];
        }
    }
}

// warp per node, lanes strided over edges, online softmax, lane merge
__global__ void k_out(const float* __restrict__ atto, const float* __restrict__ biaso,
                      float* __restrict__ out) {
    int node = (blockIdx.x * blockDim.x + threadIdx.x) >> 5;
    int lane = threadIdx.x & 31;
    if (node >= NN) return;
    float x0 = g_xlo[2 * node], x1 = g_xlo[2 * node + 1];
    float r0 = g_xro[2 * node], r1 = g_xro[2 * node + 1];
    float a0 = atto[0], a1 = atto[1];
    float sl = a0 * lrelu(x0 + r0) + a1 * lrelu(x1 + r1);

    float m, d, s0, s1;
    if (lane == 0) { m = sl; d = 1.f; s0 = x0; s1 = x1; }
    else           { m = -3.0e38f; d = 0.f; s0 = 0.f; s1 = 0.f; }

    const int start = g_rowptr[node], end = g_rowptr[node + 1];
    for (int p = start + lane; p < end; p += 32) {
        int s = g_adj[p];
        float y0 = g_xlo[2 * s], y1 = g_xlo[2 * s + 1];
        float l  = a0 * lrelu(y0 + r0) + a1 * lrelu(y1 + r1);
        float mn = fmaxf(m, l);
        float sc = __expf(m - mn);
        float w  = __expf(l - mn);
        d  = d * sc + w;
        s0 = s0 * sc + w * y0;
        s1 = s1 * sc + w * y1;
        m  = mn;
    }
#pragma unroll
    for (int o = 16; o; o >>= 1) {
        float m2 = __shfl_xor_sync(0xffffffffu, m, o);
        float d2 = __shfl_xor_sync(0xffffffffu, d, o);
        float t0 = __shfl_xor_sync(0xffffffffu, s0, o);
        float t1 = __shfl_xor_sync(0xffffffffu, s1, o);
        float mn  = fmaxf(m, m2);
        float sc1 = __expf(m - mn);
        float sc2 = __expf(m2 - mn);
        d  = d * sc1 + d2 * sc2;
        s0 = s0 * sc1 + t0 * sc2;
        s1 = s1 * sc1 + t1 * sc2;
        m  = mn;
    }
    if (lane == 0) {
        float dinv = 1.f / d;
        out[2 * node]     = s0 * dinv + biaso[0];
        out[2 * node + 1] = s1 * dinv + biaso[1];
    }
}

// ---------------- launch --------------------------------------------------------
extern "C" void kernel_launch(void* const* d_in, const int* in_sizes, int n_in,
                              void* d_out, int out_size) {
    const float* x     = (const float*)d_in[0];
    const int*   ei    = (const int*)d_in[1];
    const float* Wl0   = (const float*)d_in[2];
    const float* bl0   = (const float*)d_in[3];
    const float* Wr0   = (const float*)d_in[4];
    const float* br0   = (const float*)d_in[5];
    const float* att0  = (const float*)d_in[6];
    const float* bias0 = (const float*)d_in[7];
    const float* Wl1   = (const float*)d_in[8];
    const float* bl1   = (const float*)d_in[9];
    const float* Wr1   = (const float*)d_in[10];
    const float* br1   = (const float*)d_in[11];
    const float* att1  = (const float*)d_in[12];
    const float* bias1 = (const float*)d_in[13];
    const float* Wlo   = (const float*)d_in[14];
    const float* blo   = (const float*)d_in[15];
    const float* Wro   = (const float*)d_in[16];
    const float* bro   = (const float*)d_in[17];
    const float* atto  = (const float*)d_in[18];
    const float* biaso = (const float*)d_in[19];
    float* out = (float*)d_out;

    const int* src = ei;        // edge_index[0]
    const int* dst = ei + EE;   // edge_index[1]

    float *pxl, *pxr, *pact;
    int *pcnt, *prow, *padj;
    cudaGetSymbolAddress((void**)&pxl,  g_xl);
    cudaGetSymbolAddress((void**)&pxr,  g_xr);
    cudaGetSymbolAddress((void**)&pact, g_act);
    cudaGetSymbolAddress((void**)&pcnt, g_cnt);
    cudaGetSymbolAddress((void**)&prow, g_rowptr);
    cudaGetSymbolAddress((void**)&padj, g_adj);

    // CSR by destination
    k_zero_int<<<(NN + 255) / 256, 256>>>(pcnt, NN);
    k_count  <<<(EE + 255) / 256, 256>>>(dst, pcnt);
    k_scan   <<<1, 1024>>>(pcnt, prow);
    k_scatter<<<(EE + 255) / 256, 256>>>(dst, src, prow, pcnt, padj);

    dim3 g0(NHC / 128, (NN + 127) / 128, 2);

    // layer 0
    k_sgemm2<128, 128, 16, 8, 8><<<g0, 256>>>(x, Wl0, bl0, pxl, Wr0, br0, pxr, NN, D0, NHC);
    k_aggregate<<<(NN + 7) / 8, 256>>>(att0, bias0);

    // layer 1
    k_sgemm2<128, 128, 16, 8, 8><<<g0, 256>>>(pact, Wl1, bl1, pxl, Wr1, br1, pxr, NN, HC, NHC);
    k_aggregate<<<(NN + 7) / 8, 256>>>(att1, bias1);

    // output layer
    k_lin_out<<<(NN + 7) / 8, 256>>>(Wlo, blo, Wro, bro);
    k_out    <<<(NN + 7) / 8, 256>>>(atto, biaso, out);
}

// round 3
// speedup vs baseline: 1.9185x; 1.5252x over previous
#include <cuda_runtime.h>

#define NN   50000
#define EE   400000
#define NH   12
#define HC   32
#define D0   128
#define NHC  (NH*HC)   // 384
#define NC   2

// ---------------- scratch (static device globals) -----------------------------
__device__ float g_xl[(size_t)NN * NHC];       // 76.8 MB (fits L2)
__device__ float g_xr[(size_t)NN * NHC];       // 76.8 MB
__device__ float g_act[(size_t)NN * HC];
__device__ float g_xlo[NN * NC];
__device__ float g_xro[NN * NC];
__device__ int   g_rowptr[NN + 1];
__device__ int   g_cnt[NN];
__device__ int   g_adj[EE];                    // src node ids grouped by dst

__device__ __forceinline__ float lrelu(float v) { return v > 0.f ? v : 0.2f * v; }

__device__ __forceinline__ void ffma2(unsigned long long& d, unsigned long long a,
                                      unsigned long long b) {
    asm("fma.rn.f32x2 %0, %1, %2, %0;" : "+l"(d) : "l"(a), "l"(b));
}
__device__ __forceinline__ unsigned long long dup2(float v) {
    unsigned long long r;
    asm("mov.b64 %0, {%1, %1};" : "=l"(r) : "f"(v));
    return r;
}

// ---------------- CSR build ----------------------------------------------------
__global__ void k_count(const int* __restrict__ dst, int* cnt) {
    int i = blockIdx.x * blockDim.x + threadIdx.x;
    if (i < EE) atomicAdd(&cnt[dst[i]], 1);
}

// single-block warp-scan prefix sum over NN counts
__global__ void k_scan(const int* __restrict__ cnt, int* __restrict__ rowptr) {
    __shared__ int wsum[32];
    __shared__ int carry;
    int lane = threadIdx.x & 31, wid = threadIdx.x >> 5;
    if (threadIdx.x == 0) { carry = 0; rowptr[0] = 0; }
    __syncthreads();
    for (int base = 0; base < NN; base += 1024) {
        int i = base + threadIdx.x;
        int v = (i < NN) ? cnt[i] : 0;
        int x = v;
#pragma unroll
        for (int o = 1; o < 32; o <<= 1) {
            int t = __shfl_up_sync(0xffffffffu, x, o);
            if (lane >= o) x += t;
        }
        if (lane == 31) wsum[wid] = x;
        __syncthreads();
        if (wid == 0) {
            int s = wsum[lane];
#pragma unroll
            for (int o = 1; o < 32; o <<= 1) {
                int t = __shfl_up_sync(0xffffffffu, s, o);
                if (lane >= o) s += t;
            }
            wsum[lane] = s;
        }
        __syncthreads();
        int incl = x + (wid ? wsum[wid - 1] : 0) + carry;
        if (i < NN) rowptr[i + 1] = incl;
        int total = wsum[31];
        __syncthreads();
        if (threadIdx.x == 0) carry += total;
        __syncthreads();
    }
}

// scatter src ids grouped by dst (consumes cnt back down to zero)
__global__ void k_scatter(const int* __restrict__ dst, const int* __restrict__ src,
                          const int* __restrict__ rowptr, int* cnt, int* adj) {
    int i = blockIdx.x * blockDim.x + threadIdx.x;
    if (i < EE) {
        int d = dst[i];
        int pos = rowptr[d] + (atomicAdd(&cnt[d], -1) - 1);
        adj[pos] = src[i];
    }
}

// ---------------- f32x2 SGEMM: C = A[M,K] @ W[K,Ncol] + bias -------------------
template <int BM, int BN, int BK, int TM, int TN>
__global__ __launch_bounds__(256)
void k_sgemm2(const float* __restrict__ A,
              const float* __restrict__ Wa, const float* __restrict__ ba, float* __restrict__ Ca,
              const float* __restrict__ Wb, const float* __restrict__ bb_, float* __restrict__ Cb,
              int M, int K, int Ncol) {
    const float* W    = blockIdx.z ? Wb  : Wa;
    const float* bias = blockIdx.z ? bb_ : ba;
    float*       C    = blockIdx.z ? Cb  : Ca;

    __shared__ float As[BK][BM + 2];
    __shared__ float Bs[BK][BN];

    const int tid  = threadIdx.x;
    const int tcol = tid & 15;
    const int trow = tid >> 4;
    const int rowBase = blockIdx.y * BM;
    const int colBase = blockIdx.x * BN;

    unsigned long long acc[TM / 2][TN];
#pragma unroll
    for (int i = 0; i < TM / 2; i++)
#pragma unroll
        for (int j = 0; j < TN; j++) acc[i][j] = 0ull;

    for (int k0 = 0; k0 < K; k0 += BK) {
#pragma unroll
        for (int t = tid; t < BM * BK / 4; t += 256) {
            int r  = t >> 2;
            int c4 = (t & 3) * 4;
            int gr = rowBase + r;
            float4 v = make_float4(0.f, 0.f, 0.f, 0.f);
            if (gr < M) v = *reinterpret_cast<const float4*>(&A[(size_t)gr * K + k0 + c4]);
            As[c4 + 0][r] = v.x;
            As[c4 + 1][r] = v.y;
            As[c4 + 2][r] = v.z;
            As[c4 + 3][r] = v.w;
        }
#pragma unroll
        for (int t = tid; t < BK * BN / 4; t += 256) {
            int r  = t / (BN / 4);
            int c4 = (t % (BN / 4)) * 4;
            *reinterpret_cast<float4*>(&Bs[r][c4]) =
                *reinterpret_cast<const float4*>(&W[(size_t)(k0 + r) * Ncol + colBase + c4]);
        }
        __syncthreads();
#pragma unroll
        for (int kk = 0; kk < BK; kk++) {
            const unsigned long long* ap =
                reinterpret_cast<const unsigned long long*>(&As[kk][trow * TM]);
            unsigned long long a2[TM / 2];
#pragma unroll
            for (int i = 0; i < TM / 2; i++) a2[i] = ap[i];
            float4 b0 = *reinterpret_cast<const float4*>(&Bs[kk][tcol * TN]);
            float4 b1 = *reinterpret_cast<const float4*>(&Bs[kk][tcol * TN + 4]);
            float bj[TN] = {b0.x, b0.y, b0.z, b0.w, b1.x, b1.y, b1.z, b1.w};
#pragma unroll
            for (int j = 0; j < TN; j++) {
                unsigned long long bb = dup2(bj[j]);
#pragma unroll
                for (int i = 0; i < TM / 2; i++) ffma2(acc[i][j], a2[i], bb);
            }
        }
        __syncthreads();
    }

    float bv[TN];
#pragma unroll
    for (int j = 0; j < TN; j++) bv[j] = bias[colBase + tcol * TN + j];
#pragma unroll
    for (int i = 0; i < TM / 2; i++) {
        int gr0 = rowBase + trow * TM + 2 * i;
        if (gr0 < M) {
#pragma unroll
            for (int j = 0; j < TN; j++) {
                float2 f = *reinterpret_cast<float2*>(&acc[i][j]);
                int gc = colBase + tcol * TN + j;
                C[(size_t)gr0 * Ncol + gc] = f.x + bv[j];
                if (gr0 + 1 < M) C[(size_t)(gr0 + 1) * Ncol + gc] = f.y + bv[j];
            }
        }
    }
}

// ---------------- fused GATv2 layer (float4 head-group layout) -----------------
// warp per dst node. Lane l, group g owns head 4g+(l>>3), channels (l&7)*4..+3.
// Per edge: 3 LDG.128, 9 shfl (4 heads reduced per 3-shfl butterfly), 3 exps.
__device__ __forceinline__ float head_logit(float4 xv, float4 xr, float4 a) {
    float t = lrelu(xv.x + xr.x) * a.x
            + lrelu(xv.y + xr.y) * a.y
            + lrelu(xv.z + xr.z) * a.z
            + lrelu(xv.w + xr.w) * a.w;
    t += __shfl_xor_sync(0xffffffffu, t, 1);
    t += __shfl_xor_sync(0xffffffffu, t, 2);
    t += __shfl_xor_sync(0xffffffffu, t, 4);
    return t;   // all 8 lanes of the group hold head total
}

__global__ __launch_bounds__(256)
void k_aggregate(const float* __restrict__ att, const float* __restrict__ bias) {
    int node = (blockIdx.x * blockDim.x + threadIdx.x) >> 5;
    int lane = threadIdx.x & 31;
    if (node >= NN) return;

    const float4* xli = reinterpret_cast<const float4*>(g_xl + (size_t)node * NHC);
    const float4* xri = reinterpret_cast<const float4*>(g_xr + (size_t)node * NHC);
    const float4* a4  = reinterpret_cast<const float4*>(att);

    float4 attv[3], xrv[3], acc[3];
    float m[3], d[3];
#pragma unroll
    for (int g = 0; g < 3; g++) {
        attv[g] = a4[g * 32 + lane];
        xrv[g]  = xri[g * 32 + lane];
    }
    // self-loop initializes online state
#pragma unroll
    for (int g = 0; g < 3; g++) {
        float4 xv = xli[g * 32 + lane];
        m[g] = head_logit(xv, xrv[g], attv[g]);
        d[g] = 1.f;
        acc[g] = xv;
    }

    const int start = g_rowptr[node], end = g_rowptr[node + 1];
    for (int p = start; p < end; ++p) {
        int s = g_adj[p];
        const float4* xs = reinterpret_cast<const float4*>(g_xl + (size_t)s * NHC);
#pragma unroll
        for (int g = 0; g < 3; g++) {
            float4 xv = xs[g * 32 + lane];
            float t  = head_logit(xv, xrv[g], attv[g]);
            float mn = fmaxf(m[g], t);
            float e  = __expf(fminf(m[g], t) - mn);  // single exp
            bool  big = t > m[g];
            float pp = big ? e : 1.f;    // scale on old state
            float qq = big ? 1.f : e;    // weight on new value
            d[g] = d[g] * pp + qq;
            acc[g].x = acc[g].x * pp + qq * xv.x;
            acc[g].y = acc[g].y * pp + qq * xv.y;
            acc[g].z = acc[g].z * pp + qq * xv.z;
            acc[g].w = acc[g].w * pp + qq * xv.w;
            m[g] = mn;
        }
    }

    // mean over heads: per-g normalize, sum g locally, then sum over the 4
    // head-subgroups (lanes differing in bits 3,4 of lane id)
    float4 s4 = make_float4(0.f, 0.f, 0.f, 0.f);
#pragma unroll
    for (int g = 0; g < 3; g++) {
        float dinv = 1.f / d[g];
        s4.x += acc[g].x * dinv;
        s4.y += acc[g].y * dinv;
        s4.z += acc[g].z * dinv;
        s4.w += acc[g].w * dinv;
    }
#pragma unroll
    for (int o = 8; o <= 16; o <<= 1) {
        s4.x += __shfl_xor_sync(0xffffffffu, s4.x, o);
        s4.y += __shfl_xor_sync(0xffffffffu, s4.y, o);
        s4.z += __shfl_xor_sync(0xffffffffu, s4.z, o);
        s4.w += __shfl_xor_sync(0xffffffffu, s4.w, o);
    }
    if (lane < 8) {
        float4 b = reinterpret_cast<const float4*>(bias)[lane];
        float4 o4;
        o4.x = s4.x * (1.f / NH) + b.x;
        o4.y = s4.y * (1.f / NH) + b.y;
        o4.z = s4.z * (1.f / NH) + b.z;
        o4.w = s4.w * (1.f / NH) + b.w;
        o4.x = o4.x > 0.f ? o4.x : (__expf(o4.x) - 1.f);
        o4.y = o4.y > 0.f ? o4.y : (__expf(o4.y) - 1.f);
        o4.z = o4.z > 0.f ? o4.z : (__expf(o4.z) - 1.f);
        o4.w = o4.w > 0.f ? o4.w : (__expf(o4.w) - 1.f);
        reinterpret_cast<float4*>(g_act + (size_t)node * HC)[lane] = o4;
    }
}

// ---------------- output GATv2 layer (heads=1, C=2) ----------------------------
__global__ void k_lin_out(const float* __restrict__ Wl, const float* __restrict__ bl,
                          const float* __restrict__ Wr, const float* __restrict__ br) {
    int node = (blockIdx.x * blockDim.x + threadIdx.x) >> 5;
    int lane = threadIdx.x & 31;
    if (node >= NN) return;
    float hv = g_act[(size_t)node * HC + lane];
#pragma unroll
    for (int j = 0; j < NC; j++) {
        float a = hv * Wl[lane * NC + j];
        float b = hv * Wr[lane * NC + j];
#pragma unroll
        for (int o = 16; o; o >>= 1) {
            a += __shfl_xor_sync(0xffffffffu, a, o);
            b += __shfl_xor_sync(0xffffffffu, b, o);
        }
        if (lane == 0) {
            g_xlo[node * NC + j] = a + bl[j];
            g_xro[node * NC + j] = b + br[j];
        }
    }
}

__global__ void k_out(const float* __restrict__ atto, const float* __restrict__ biaso,
                      float* __restrict__ out) {
    int node = (blockIdx.x * blockDim.x + threadIdx.x) >> 5;
    int lane = threadIdx.x & 31;
    if (node >= NN) return;
    float x0 = g_xlo[2 * node], x1 = g_xlo[2 * node + 1];
    float r0 = g_xro[2 * node], r1 = g_xro[2 * node + 1];
    float a0 = atto[0], a1 = atto[1];
    float sl = a0 * lrelu(x0 + r0) + a1 * lrelu(x1 + r1);

    float m, d, s0, s1;
    if (lane == 0) { m = sl; d = 1.f; s0 = x0; s1 = x1; }
    else           { m = -3.0e38f; d = 0.f; s0 = 0.f; s1 = 0.f; }

    const int start = g_rowptr[node], end = g_rowptr[node + 1];
    for (int p = start + lane; p < end; p += 32) {
        int s = g_adj[p];
        float y0 = g_xlo[2 * s], y1 = g_xlo[2 * s + 1];
        float l  = a0 * lrelu(y0 + r0) + a1 * lrelu(y1 + r1);
        float mn = fmaxf(m, l);
        float sc = __expf(m - mn);
        float w  = __expf(l - mn);
        d  = d * sc + w;
        s0 = s0 * sc + w * y0;
        s1 = s1 * sc + w * y1;
        m  = mn;
    }
#pragma unroll
    for (int o = 16; o; o >>= 1) {
        float m2 = __shfl_xor_sync(0xffffffffu, m, o);
        float d2 = __shfl_xor_sync(0xffffffffu, d, o);
        float t0 = __shfl_xor_sync(0xffffffffu, s0, o);
        float t1 = __shfl_xor_sync(0xffffffffu, s1, o);
        float mn  = fmaxf(m, m2);
        float sc1 = __expf(m - mn);
        float sc2 = __expf(m2 - mn);
        d  = d * sc1 + d2 * sc2;
        s0 = s0 * sc1 + t0 * sc2;
        s1 = s1 * sc1 + t1 * sc2;
        m  = mn;
    }
    if (lane == 0) {
        float dinv = 1.f / d;
        out[2 * node]     = s0 * dinv + biaso[0];
        out[2 * node + 1] = s1 * dinv + biaso[1];
    }
}

// ---------------- launch --------------------------------------------------------
extern "C" void kernel_launch(void* const* d_in, const int* in_sizes, int n_in,
                              void* d_out, int out_size) {
    const float* x     = (const float*)d_in[0];
    const int*   ei    = (const int*)d_in[1];
    const float* Wl0   = (const float*)d_in[2];
    const float* bl0   = (const float*)d_in[3];
    const float* Wr0   = (const float*)d_in[4];
    const float* br0   = (const float*)d_in[5];
    const float* att0  = (const float*)d_in[6];
    const float* bias0 = (const float*)d_in[7];
    const float* Wl1   = (const float*)d_in[8];
    const float* bl1   = (const float*)d_in[9];
    const float* Wr1   = (const float*)d_in[10];
    const float* br1   = (const float*)d_in[11];
    const float* att1  = (const float*)d_in[12];
    const float* bias1 = (const float*)d_in[13];
    const float* Wlo   = (const float*)d_in[14];
    const float* blo   = (const float*)d_in[15];
    const float* Wro   = (const float*)d_in[16];
    const float* bro   = (const float*)d_in[17];
    const float* atto  = (const float*)d_in[18];
    const float* biaso = (const float*)d_in[19];
    float* out = (float*)d_out;

    const int* src = ei;        // edge_index[0]
    const int* dst = ei + EE;   // edge_index[1]

    float *pxl, *pxr, *pact;
    int *pcnt, *prow, *padj;
    cudaGetSymbolAddress((void**)&pxl,  g_xl);
    cudaGetSymbolAddress((void**)&pxr,  g_xr);
    cudaGetSymbolAddress((void**)&pact, g_act);
    cudaGetSymbolAddress((void**)&pcnt, g_cnt);
    cudaGetSymbolAddress((void**)&prow, g_rowptr);
    cudaGetSymbolAddress((void**)&padj, g_adj);

    // CSR by destination
    cudaMemsetAsync(pcnt, 0, NN * sizeof(int));
    k_count  <<<(EE + 255) / 256, 256>>>(dst, pcnt);
    k_scan   <<<1, 1024>>>(pcnt, prow);
    k_scatter<<<(EE + 255) / 256, 256>>>(dst, src, prow, pcnt, padj);

    dim3 g0(NHC / 128, (NN + 127) / 128, 2);

    // layer 0
    k_sgemm2<128, 128, 16, 8, 8><<<g0, 256>>>(x, Wl0, bl0, pxl, Wr0, br0, pxr, NN, D0, NHC);
    k_aggregate<<<(NN + 7) / 8, 256>>>(att0, bias0);

    // layer 1
    k_sgemm2<128, 128, 16, 8, 8><<<g0, 256>>>(pact, Wl1, bl1, pxl, Wr1, br1, pxr, NN, HC, NHC);
    k_aggregate<<<(NN + 7) / 8, 256>>>(att1, bias1);

    // output layer
    k_lin_out<<<(NN + 7) / 8, 256>>>(Wlo, blo, Wro, bro);
    k_out    <<<(NN + 7) / 8, 256>>>(atto, biaso, out);
}

// round 5
// speedup vs baseline: 2.4613x; 1.2829x over previous
#include <cuda_runtime.h>
#include <cuda_bf16.h>
#include <cstdint>

#define NN   50000
#define EE   400000
#define NH   12
#define HC   32
#define D0   128
#define NHC  (NH*HC)   // 384
#define NC   2

// ---------------- scratch (static device globals) -----------------------------
__device__ float g_xl[(size_t)NN * NHC];       // 76.8 MB (fits L2)
__device__ float g_xr[(size_t)NN * NHC];       // 76.8 MB
__device__ float g_act[(size_t)NN * HC];
__device__ float g_xlo[NN * NC];
__device__ float g_xro[NN * NC];
__device__ int   g_rowptr[NN + 1];
__device__ int   g_cnt[NN];
__device__ int   g_adj[EE];                    // src node ids grouped by dst

__device__ __forceinline__ float lrelu(float v) { return v > 0.f ? v : 0.2f * v; }

__device__ __forceinline__ uint32_t smem_u32(const void* p) {
    uint32_t a;
    asm("{ .reg .u64 t; cvta.to.shared.u64 t, %1; cvt.u32.u64 %0, t; }" : "=r"(a) : "l"(p));
    return a;
}
__device__ __forceinline__ void ldsm4(uint32_t* r, uint32_t addr) {
    asm volatile("ldmatrix.sync.aligned.m8n8.x4.shared.b16 {%0,%1,%2,%3}, [%4];"
                 : "=r"(r[0]), "=r"(r[1]), "=r"(r[2]), "=r"(r[3]) : "r"(addr));
}
__device__ __forceinline__ void mma_bf16(float* c, const uint32_t* a, uint32_t b0, uint32_t b1) {
    asm volatile(
        "mma.sync.aligned.m16n8k16.row.col.f32.bf16.bf16.f32 "
        "{%0,%1,%2,%3}, {%4,%5,%6,%7}, {%8,%9}, {%0,%1,%2,%3};"
        : "+f"(c[0]), "+f"(c[1]), "+f"(c[2]), "+f"(c[3])
        : "r"(a[0]), "r"(a[1]), "r"(a[2]), "r"(a[3]), "r"(b0), "r"(b1));
}
__device__ __forceinline__ uint32_t bf2bits(__nv_bfloat162 h) {
    return *reinterpret_cast<uint32_t*>(&h);
}

// ---------------- bf16x3 HMMA GEMM: C[M,384] = A[M,K] @ W[K,384] + bias --------
// BM=128, BN=64, full-K resident hi/lo tiles. blockIdx.z picks weight set.
template <int K>
__global__ __launch_bounds__(256, 2)
void k_gemm_mma(const float* __restrict__ A,
                const float* __restrict__ Wa, const float* __restrict__ ba, float* __restrict__ Ca,
                const float* __restrict__ Wb, const float* __restrict__ bb_, float* __restrict__ Cb,
                int M, int Ncol) {
    constexpr int BM = 128, BN = 64;
    constexpr int ST  = K * 2 + 16;        // smem row stride (bytes), conflict-free
    constexpr int SZA = BM * ST;
    constexpr int SZB = BN * ST;

    extern __shared__ char smem[];
    char* sAh = smem;                       // +0
    char* sAl = smem + SZA;
    char* sBh = smem + 2 * SZA;
    char* sBl = smem + 2 * SZA + SZB;

    const float* W    = blockIdx.z ? Wb  : Wa;
    const float* bias = blockIdx.z ? bb_ : ba;
    float*       C    = blockIdx.z ? Cb  : Ca;
    const int rowBase = blockIdx.y * BM;
    const int colBase = blockIdx.x * BN;
    const int tid  = threadIdx.x;
    const int wid  = tid >> 5;
    const int lane = tid & 31;
    const int wm   = wid & 3;              // warp row (32 rows each)
    const int wn   = wid >> 2;             // warp col (32 cols each)

    // ---- load + split A tile ----
    for (int i = tid; i < BM * (K / 4); i += 256) {
        int r  = i / (K / 4);
        int c4 = (i % (K / 4)) * 4;
        int gr = rowBase + r;
        float4 v = make_float4(0.f, 0.f, 0.f, 0.f);
        if (gr < M) v = *reinterpret_cast<const float4*>(&A[(size_t)gr * K + c4]);
        __nv_bfloat162 h01 = __floats2bfloat162_rn(v.x, v.y);
        __nv_bfloat162 h23 = __floats2bfloat162_rn(v.z, v.w);
        float2 f01 = __bfloat1622float2(h01);
        float2 f23 = __bfloat1622float2(h23);
        __nv_bfloat162 l01 = __floats2bfloat162_rn(v.x - f01.x, v.y - f01.y);
        __nv_bfloat162 l23 = __floats2bfloat162_rn(v.z - f23.x, v.w - f23.y);
        char* ph = sAh + r * ST + c4 * 2;
        char* pl = sAl + r * ST + c4 * 2;
        *reinterpret_cast<uint32_t*>(ph)     = bf2bits(h01);
        *reinterpret_cast<uint32_t*>(ph + 4) = bf2bits(h23);
        *reinterpret_cast<uint32_t*>(pl)     = bf2bits(l01);
        *reinterpret_cast<uint32_t*>(pl + 4) = bf2bits(l23);
    }
    // ---- load + split B tile: B'[n][k] = W[k][colBase+n] ----
    for (int i = tid; i < K * (BN / 4); i += 256) {
        int k  = i >> 4;                   // BN/4 = 16 float4 per k-row
        int n0 = (i & 15) * 4;
        float4 v = *reinterpret_cast<const float4*>(&W[(size_t)k * Ncol + colBase + n0]);
        float vv[4] = {v.x, v.y, v.z, v.w};
#pragma unroll
        for (int j = 0; j < 4; j++) {
            __nv_bfloat16 h = __float2bfloat16(vv[j]);
            float hf = __bfloat162float(h);
            __nv_bfloat16 l = __float2bfloat16(vv[j] - hf);
            *reinterpret_cast<__nv_bfloat16*>(sBh + (n0 + j) * ST + k * 2) = h;
            *reinterpret_cast<__nv_bfloat16*>(sBl + (n0 + j) * ST + k * 2) = l;
        }
    }
    __syncthreads();

    const uint32_t sb = smem_u32(smem);
    const int g  = lane >> 3;
    const int ri = lane & 7;

    float acc[2][4][4];
#pragma unroll
    for (int mt = 0; mt < 2; mt++)
#pragma unroll
        for (int nt = 0; nt < 4; nt++)
#pragma unroll
            for (int q = 0; q < 4; q++) acc[mt][nt][q] = 0.f;

#pragma unroll
    for (int kk = 0; kk < K / 16; kk++) {
        uint32_t aH[2][4], aL[2][4], bH[2][4], bL[2][4];
#pragma unroll
        for (int mt = 0; mt < 2; mt++) {
            int row = wm * 32 + mt * 16 + ri + (g & 1) * 8;
            int col = kk * 16 + (g >> 1) * 8;
            uint32_t ad = sb + row * ST + col * 2;
            ldsm4(aH[mt], ad);
            ldsm4(aL[mt], ad + SZA);
        }
#pragma unroll
        for (int p = 0; p < 2; p++) {
            int row = wn * 32 + p * 16 + ri + (g >> 1) * 8;
            int col = kk * 16 + (g & 1) * 8;
            uint32_t bd = sb + 2 * SZA + row * ST + col * 2;
            ldsm4(bH[p], bd);
            ldsm4(bL[p], bd + SZB);
        }
#pragma unroll
        for (int mt = 0; mt < 2; mt++)
#pragma unroll
            for (int nt = 0; nt < 4; nt++) {
                int p = nt >> 1, o = (nt & 1) * 2;
                mma_bf16(acc[mt][nt], aH[mt], bH[p][o], bH[p][o + 1]);
                mma_bf16(acc[mt][nt], aH[mt], bL[p][o], bL[p][o + 1]);
                mma_bf16(acc[mt][nt], aL[mt], bH[p][o], bH[p][o + 1]);
            }
    }

    // ---- epilogue: direct global stores with bias ----
#pragma unroll
    for (int mt = 0; mt < 2; mt++) {
#pragma unroll
        for (int nt = 0; nt < 4; nt++) {
            int gr = rowBase + wm * 32 + mt * 16 + (lane >> 2);
            int gc = colBase + wn * 32 + nt * 8 + (lane & 3) * 2;
            float b0 = bias[gc], b1 = bias[gc + 1];
            if (gr < M) {
                float2 o = make_float2(acc[mt][nt][0] + b0, acc[mt][nt][1] + b1);
                *reinterpret_cast<float2*>(&C[(size_t)gr * Ncol + gc]) = o;
            }
            if (gr + 8 < M) {
                float2 o = make_float2(acc[mt][nt][2] + b0, acc[mt][nt][3] + b1);
                *reinterpret_cast<float2*>(&C[(size_t)(gr + 8) * Ncol + gc]) = o;
            }
        }
    }
}

// ---------------- CSR build ----------------------------------------------------
__global__ void k_count(const int* __restrict__ dst, int* cnt) {
    int i = blockIdx.x * blockDim.x + threadIdx.x;
    if (i < EE) atomicAdd(&cnt[dst[i]], 1);
}

__global__ void k_scan(const int* __restrict__ cnt, int* __restrict__ rowptr) {
    __shared__ int wsum[32];
    __shared__ int carry;
    int lane = threadIdx.x & 31, wid = threadIdx.x >> 5;
    if (threadIdx.x == 0) { carry = 0; rowptr[0] = 0; }
    __syncthreads();
    for (int base = 0; base < NN; base += 1024) {
        int i = base + threadIdx.x;
        int v = (i < NN) ? cnt[i] : 0;
        int x = v;
#pragma unroll
        for (int o = 1; o < 32; o <<= 1) {
            int t = __shfl_up_sync(0xffffffffu, x, o);
            if (lane >= o) x += t;
        }
        if (lane == 31) wsum[wid] = x;
        __syncthreads();
        if (wid == 0) {
            int s = wsum[lane];
#pragma unroll
            for (int o = 1; o < 32; o <<= 1) {
                int t = __shfl_up_sync(0xffffffffu, s, o);
                if (lane >= o) s += t;
            }
            wsum[lane] = s;
        }
        __syncthreads();
        int incl = x + (wid ? wsum[wid - 1] : 0) + carry;
        if (i < NN) rowptr[i + 1] = incl;
        int total = wsum[31];
        __syncthreads();
        if (threadIdx.x == 0) carry += total;
        __syncthreads();
    }
}

__global__ void k_scatter(const int* __restrict__ dst, const int* __restrict__ src,
                          const int* __restrict__ rowptr, int* cnt, int* adj) {
    int i = blockIdx.x * blockDim.x + threadIdx.x;
    if (i < EE) {
        int d = dst[i];
        int pos = rowptr[d] + (atomicAdd(&cnt[d], -1) - 1);
        adj[pos] = src[i];
    }
}

// ---------------- fused GATv2 layer (float4 head-group layout) -----------------
__device__ __forceinline__ float head_logit(float4 xv, float4 xr, float4 a) {
    float t = lrelu(xv.x + xr.x) * a.x
            + lrelu(xv.y + xr.y) * a.y
            + lrelu(xv.z + xr.z) * a.z
            + lrelu(xv.w + xr.w) * a.w;
    t += __shfl_xor_sync(0xffffffffu, t, 1);
    t += __shfl_xor_sync(0xffffffffu, t, 2);
    t += __shfl_xor_sync(0xffffffffu, t, 4);
    return t;
}

__global__ __launch_bounds__(256)
void k_aggregate(const float* __restrict__ att, const float* __restrict__ bias) {
    int node = (blockIdx.x * blockDim.x + threadIdx.x) >> 5;
    int lane = threadIdx.x & 31;
    if (node >= NN) return;

    const float4* xli = reinterpret_cast<const float4*>(g_xl + (size_t)node * NHC);
    const float4* xri = reinterpret_cast<const float4*>(g_xr + (size_t)node * NHC);
    const float4* a4  = reinterpret_cast<const float4*>(att);

    float4 attv[3], xrv[3], acc[3];
    float m[3], d[3];
#pragma unroll
    for (int g = 0; g < 3; g++) {
        attv[g] = a4[g * 32 + lane];
        xrv[g]  = xri[g * 32 + lane];
    }
#pragma unroll
    for (int g = 0; g < 3; g++) {
        float4 xv = xli[g * 32 + lane];
        m[g] = head_logit(xv, xrv[g], attv[g]);
        d[g] = 1.f;
        acc[g] = xv;
    }

    const int start = g_rowptr[node], end = g_rowptr[node + 1];
    for (int p = start; p < end; ++p) {
        int s = g_adj[p];
        const float4* xs = reinterpret_cast<const float4*>(g_xl + (size_t)s * NHC);
#pragma unroll
        for (int g = 0; g < 3; g++) {
            float4 xv = xs[g * 32 + lane];
            float t  = head_logit(xv, xrv[g], attv[g]);
            float mn = fmaxf(m[g], t);
            float e  = __expf(fminf(m[g], t) - mn);
            bool  big = t > m[g];
            float pp = big ? e : 1.f;
            float qq = big ? 1.f : e;
            d[g] = d[g] * pp + qq;
            acc[g].x = acc[g].x * pp + qq * xv.x;
            acc[g].y = acc[g].y * pp + qq * xv.y;
            acc[g].z = acc[g].z * pp + qq * xv.z;
            acc[g].w = acc[g].w * pp + qq * xv.w;
            m[g] = mn;
        }
    }

    float4 s4 = make_float4(0.f, 0.f, 0.f, 0.f);
#pragma unroll
    for (int g = 0; g < 3; g++) {
        float dinv = 1.f / d[g];
        s4.x += acc[g].x * dinv;
        s4.y += acc[g].y * dinv;
        s4.z += acc[g].z * dinv;
        s4.w += acc[g].w * dinv;
    }
#pragma unroll
    for (int o = 8; o <= 16; o <<= 1) {
        s4.x += __shfl_xor_sync(0xffffffffu, s4.x, o);
        s4.y += __shfl_xor_sync(0xffffffffu, s4.y, o);
        s4.z += __shfl_xor_sync(0xffffffffu, s4.z, o);
        s4.w += __shfl_xor_sync(0xffffffffu, s4.w, o);
    }
    if (lane < 8) {
        float4 b = reinterpret_cast<const float4*>(bias)[lane];
        float4 o4;
        o4.x = s4.x * (1.f / NH) + b.x;
        o4.y = s4.y * (1.f / NH) + b.y;
        o4.z = s4.z * (1.f / NH) + b.z;
        o4.w = s4.w * (1.f / NH) + b.w;
        o4.x = o4.x > 0.f ? o4.x : (__expf(o4.x) - 1.f);
        o4.y = o4.y > 0.f ? o4.y : (__expf(o4.y) - 1.f);
        o4.z = o4.z > 0.f ? o4.z : (__expf(o4.z) - 1.f);
        o4.w = o4.w > 0.f ? o4.w : (__expf(o4.w) - 1.f);
        reinterpret_cast<float4*>(g_act + (size_t)node * HC)[lane] = o4;
    }
}

// ---------------- output GATv2 layer (heads=1, C=2) ----------------------------
__global__ void k_lin_out(const float* __restrict__ Wl, const float* __restrict__ bl,
                          const float* __restrict__ Wr, const float* __restrict__ br) {
    int node = (blockIdx.x * blockDim.x + threadIdx.x) >> 5;
    int lane = threadIdx.x & 31;
    if (node >= NN) return;
    float hv = g_act[(size_t)node * HC + lane];
#pragma unroll
    for (int j = 0; j < NC; j++) {
        float a = hv * Wl[lane * NC + j];
        float b = hv * Wr[lane * NC + j];
#pragma unroll
        for (int o = 16; o; o >>= 1) {
            a += __shfl_xor_sync(0xffffffffu, a, o);
            b += __shfl_xor_sync(0xffffffffu, b, o);
        }
        if (lane == 0) {
            g_xlo[node * NC + j] = a + bl[j];
            g_xro[node * NC + j] = b + br[j];
        }
    }
}

__global__ void k_out(const float* __restrict__ atto, const float* __restrict__ biaso,
                      float* __restrict__ out) {
    int node = (blockIdx.x * blockDim.x + threadIdx.x) >> 5;
    int lane = threadIdx.x & 31;
    if (node >= NN) return;
    float x0 = g_xlo[2 * node], x1 = g_xlo[2 * node + 1];
    float r0 = g_xro[2 * node], r1 = g_xro[2 * node + 1];
    float a0 = atto[0], a1 = atto[1];
    float sl = a0 * lrelu(x0 + r0) + a1 * lrelu(x1 + r1);

    float m, d, s0, s1;
    if (lane == 0) { m = sl; d = 1.f; s0 = x0; s1 = x1; }
    else           { m = -3.0e38f; d = 0.f; s0 = 0.f; s1 = 0.f; }

    const int start = g_rowptr[node], end = g_rowptr[node + 1];
    for (int p = start + lane; p < end; p += 32) {
        int s = g_adj[p];
        float y0 = g_xlo[2 * s], y1 = g_xlo[2 * s + 1];
        float l  = a0 * lrelu(y0 + r0) + a1 * lrelu(y1 + r1);
        float mn = fmaxf(m, l);
        float sc = __expf(m - mn);
        float w  = __expf(l - mn);
        d  = d * sc + w;
        s0 = s0 * sc + w * y0;
        s1 = s1 * sc + w * y1;
        m  = mn;
    }
#pragma unroll
    for (int o = 16; o; o >>= 1) {
        float m2 = __shfl_xor_sync(0xffffffffu, m, o);
        float d2 = __shfl_xor_sync(0xffffffffu, d, o);
        float t0 = __shfl_xor_sync(0xffffffffu, s0, o);
        float t1 = __shfl_xor_sync(0xffffffffu, s1, o);
        float mn  = fmaxf(m, m2);
        float sc1 = __expf(m - mn);
        float sc2 = __expf(m2 - mn);
        d  = d * sc1 + d2 * sc2;
        s0 = s0 * sc1 + t0 * sc2;
        s1 = s1 * sc1 + t1 * sc2;
        m  = mn;
    }
    if (lane == 0) {
        float dinv = 1.f / d;
        out[2 * node]     = s0 * dinv + biaso[0];
        out[2 * node + 1] = s1 * dinv + biaso[1];
    }
}

// ---------------- launch --------------------------------------------------------
extern "C" void kernel_launch(void* const* d_in, const int* in_sizes, int n_in,
                              void* d_out, int out_size) {
    const float* x     = (const float*)d_in[0];
    const int*   ei    = (const int*)d_in[1];
    const float* Wl0   = (const float*)d_in[2];
    const float* bl0   = (const float*)d_in[3];
    const float* Wr0   = (const float*)d_in[4];
    const float* br0   = (const float*)d_in[5];
    const float* att0  = (const float*)d_in[6];
    const float* bias0 = (const float*)d_in[7];
    const float* Wl1   = (const float*)d_in[8];
    const float* bl1   = (const float*)d_in[9];
    const float* Wr1   = (const float*)d_in[10];
    const float* br1   = (const float*)d_in[11];
    const float* att1  = (const float*)d_in[12];
    const float* bias1 = (const float*)d_in[13];
    const float* Wlo   = (const float*)d_in[14];
    const float* blo   = (const float*)d_in[15];
    const float* Wro   = (const float*)d_in[16];
    const float* bro   = (const float*)d_in[17];
    const float* atto  = (const float*)d_in[18];
    const float* biaso = (const float*)d_in[19];
    float* out = (float*)d_out;

    const int* src = ei;        // edge_index[0]
    const int* dst = ei + EE;   // edge_index[1]

    float *pxl, *pxr, *pact;
    int *pcnt, *prow, *padj;
    cudaGetSymbolAddress((void**)&pxl,  g_xl);
    cudaGetSymbolAddress((void**)&pxr,  g_xr);
    cudaGetSymbolAddress((void**)&pact, g_act);
    cudaGetSymbolAddress((void**)&pcnt, g_cnt);
    cudaGetSymbolAddress((void**)&prow, g_rowptr);
    cudaGetSymbolAddress((void**)&padj, g_adj);

    // dynamic SMEM: full-K hi/lo tiles
    const int st128 = 128 * 2 + 16, st32 = 32 * 2 + 16;
    const int smem128 = 2 * (128 * st128) + 2 * (64 * st128);  // 104448
    const int smem32  = 2 * (128 * st32)  + 2 * (64 * st32);   // 30720
    cudaFuncSetAttribute(k_gemm_mma<128>, cudaFuncAttributeMaxDynamicSharedMemorySize, smem128);
    cudaFuncSetAttribute(k_gemm_mma<32>,  cudaFuncAttributeMaxDynamicSharedMemorySize, smem32);

    // CSR by destination
    cudaMemsetAsync(pcnt, 0, NN * sizeof(int));
    k_count  <<<(EE + 255) / 256, 256>>>(dst, pcnt);
    k_scan   <<<1, 1024>>>(pcnt, prow);
    k_scatter<<<(EE + 255) / 256, 256>>>(dst, src, prow, pcnt, padj);

    dim3 gg(NHC / 64, (NN + 127) / 128, 2);

    // layer 0
    k_gemm_mma<128><<<gg, 256, smem128>>>(x, Wl0, bl0, pxl, Wr0, br0, pxr, NN, NHC);
    k_aggregate<<<(NN + 7) / 8, 256>>>(att0, bias0);

    // layer 1
    k_gemm_mma<32><<<gg, 256, smem32>>>(pact, Wl1, bl1, pxl, Wr1, br1, pxr, NN, NHC);
    k_aggregate<<<(NN + 7) / 8, 256>>>(att1, bias1);

    // output layer
    k_lin_out<<<(NN + 7) / 8, 256>>>(Wlo, blo, Wro, bro);
    k_out    <<<(NN + 7) / 8, 256>>>(atto, biaso, out);
}

// round 6
// speedup vs baseline: 2.9271x; 1.1892x over previous
#include <cuda_runtime.h>
#include <cuda_bf16.h>
#include <cstdint>

#define NN   50000
#define EE   400000
#define NH   12
#define HC   32
#define D0   128
#define NHC  (NH*HC)   // 384
#define NC   2

// ---------------- scratch (static device globals) -----------------------------
__device__ float g_xl[(size_t)NN * NHC];       // 76.8 MB (fits L2)
__device__ float g_xr[(size_t)NN * NHC];       // 76.8 MB
__device__ float g_act[(size_t)NN * HC];
__device__ float g_xlo[NN * NC];
__device__ float g_xro[NN * NC];
__device__ int   g_rowptr[NN + 1];
__device__ int   g_cnt[NN];
__device__ int   g_adj[EE];                    // src node ids grouped by dst

// pre-split bf16 operands
__device__ __nv_bfloat16 g_ah[(size_t)NN * D0];        // A hi (K=128 max)
__device__ __nv_bfloat16 g_al[(size_t)NN * D0];        // A lo
__device__ __nv_bfloat16 g_wh[2 * NHC * D0];           // W^T hi, [z][n][k]
__device__ __nv_bfloat16 g_wl[2 * NHC * D0];           // W^T lo

__device__ __forceinline__ float lrelu(float v) { return v > 0.f ? v : 0.2f * v; }

__device__ __forceinline__ uint32_t smem_u32(const void* p) {
    uint32_t a;
    asm("{ .reg .u64 t; cvta.to.shared.u64 t, %1; cvt.u32.u64 %0, t; }" : "=r"(a) : "l"(p));
    return a;
}
__device__ __forceinline__ void ldsm4(uint32_t* r, uint32_t addr) {
    asm volatile("ldmatrix.sync.aligned.m8n8.x4.shared.b16 {%0,%1,%2,%3}, [%4];"
                 : "=r"(r[0]), "=r"(r[1]), "=r"(r[2]), "=r"(r[3]) : "r"(addr));
}
__device__ __forceinline__ void mma_bf16(float* c, const uint32_t* a, uint32_t b0, uint32_t b1) {
    asm volatile(
        "mma.sync.aligned.m16n8k16.row.col.f32.bf16.bf16.f32 "
        "{%0,%1,%2,%3}, {%4,%5,%6,%7}, {%8,%9}, {%0,%1,%2,%3};"
        : "+f"(c[0]), "+f"(c[1]), "+f"(c[2]), "+f"(c[3])
        : "r"(a[0]), "r"(a[1]), "r"(a[2]), "r"(a[3]), "r"(b0), "r"(b1));
}

// ---------------- split kernels -------------------------------------------------
// A[M,K] f32 -> g_ah/g_al bf16 [M,K]; float4-in, uint2-out (coalesced both sides)
template <int K>
__global__ void k_cvtA(const float* __restrict__ A, int M) {
    int i = blockIdx.x * blockDim.x + threadIdx.x;       // float4 index
    if (i >= M * K / 4) return;
    float4 v = reinterpret_cast<const float4*>(A)[i];
    __nv_bfloat162 h01 = __floats2bfloat162_rn(v.x, v.y);
    __nv_bfloat162 h23 = __floats2bfloat162_rn(v.z, v.w);
    float2 f01 = __bfloat1622float2(h01);
    float2 f23 = __bfloat1622float2(h23);
    __nv_bfloat162 l01 = __floats2bfloat162_rn(v.x - f01.x, v.y - f01.y);
    __nv_bfloat162 l23 = __floats2bfloat162_rn(v.z - f23.x, v.w - f23.y);
    uint2 h = make_uint2(*reinterpret_cast<uint32_t*>(&h01), *reinterpret_cast<uint32_t*>(&h23));
    uint2 l = make_uint2(*reinterpret_cast<uint32_t*>(&l01), *reinterpret_cast<uint32_t*>(&l23));
    reinterpret_cast<uint2*>(g_ah)[i] = h;
    reinterpret_cast<uint2*>(g_al)[i] = l;
}

// W[K,NHC] f32 -> Wt hi/lo bf16 [n][k] at slot z (transpose + split)
template <int K>
__global__ void k_cvtW(const float* __restrict__ Wa, const float* __restrict__ Wb) {
    int i = blockIdx.x * blockDim.x + threadIdx.x;       // over 2*NHC*K
    if (i >= 2 * NHC * K) return;
    int z = i / (NHC * K);
    int r = i % (NHC * K);
    int n = r / K, k = r % K;
    const float* W = z ? Wb : Wa;
    float v = W[(size_t)k * NHC + n];
    __nv_bfloat16 h = __float2bfloat16(v);
    __nv_bfloat16 l = __float2bfloat16(v - __bfloat162float(h));
    g_wh[(size_t)z * NHC * K + (size_t)n * K + k] = h;
    g_wl[(size_t)z * NHC * K + (size_t)n * K + k] = l;
}

// ---------------- bf16x3 HMMA GEMM: C[M,384] = A[M,K] @ W[K,384] + bias --------
// Inputs pre-split bf16. BM=128, BN=64. blockIdx.z picks weight set / output.
template <int K>
__global__ __launch_bounds__(256, 2)
void k_gemm_mma(const float* __restrict__ ba, float* __restrict__ Ca,
                const float* __restrict__ bb_, float* __restrict__ Cb,
                int M, int Ncol) {
    constexpr int BM = 128, BN = 64;
    constexpr int ST  = K * 2 + 16;        // smem row stride bytes (16B-aligned)
    constexpr int SZA = BM * ST;
    constexpr int SZB = BN * ST;
    constexpr int KV  = K / 8;             // uint4 (8 bf16) per row

    extern __shared__ char smem[];
    char* sAh = smem;
    char* sAl = smem + SZA;
    char* sBh = smem + 2 * SZA;
    char* sBl = smem + 2 * SZA + SZB;

    const float* bias = blockIdx.z ? bb_ : ba;
    float*       C    = blockIdx.z ? Cb  : Ca;
    const __nv_bfloat16* wh = g_wh + (size_t)blockIdx.z * NHC * K;
    const __nv_bfloat16* wl = g_wl + (size_t)blockIdx.z * NHC * K;

    const int rowBase = blockIdx.y * BM;
    const int colBase = blockIdx.x * BN;
    const int tid  = threadIdx.x;
    const int wid  = tid >> 5;
    const int lane = tid & 31;
    const int wm   = wid & 3;
    const int wn   = wid >> 2;

    // ---- A tile: pure uint4 copy of pre-split bf16 ----
    for (int i = tid; i < BM * KV; i += 256) {
        int r  = i / KV;
        int c  = i % KV;
        int gr = rowBase + r;
        uint4 h = make_uint4(0, 0, 0, 0), l = make_uint4(0, 0, 0, 0);
        if (gr < M) {
            h = reinterpret_cast<const uint4*>(g_ah + (size_t)gr * K)[c];
            l = reinterpret_cast<const uint4*>(g_al + (size_t)gr * K)[c];
        }
        *reinterpret_cast<uint4*>(sAh + r * ST + c * 16) = h;
        *reinterpret_cast<uint4*>(sAl + r * ST + c * 16) = l;
    }
    // ---- B tile: coalesced copy of transposed pre-split weights ----
    for (int i = tid; i < BN * KV; i += 256) {
        int n = i / KV;
        int c = i % KV;
        *reinterpret_cast<uint4*>(sBh + n * ST + c * 16) =
            reinterpret_cast<const uint4*>(wh + (size_t)(colBase + n) * K)[c];
        *reinterpret_cast<uint4*>(sBl + n * ST + c * 16) =
            reinterpret_cast<const uint4*>(wl + (size_t)(colBase + n) * K)[c];
    }
    __syncthreads();

    const uint32_t sb = smem_u32(smem);
    const int g  = lane >> 3;
    const int ri = lane & 7;

    float acc[2][4][4];
#pragma unroll
    for (int mt = 0; mt < 2; mt++)
#pragma unroll
        for (int nt = 0; nt < 4; nt++)
#pragma unroll
            for (int q = 0; q < 4; q++) acc[mt][nt][q] = 0.f;

#pragma unroll
    for (int kk = 0; kk < K / 16; kk++) {
        uint32_t aH[2][4], aL[2][4], bH[2][4], bL[2][4];
#pragma unroll
        for (int mt = 0; mt < 2; mt++) {
            int row = wm * 32 + mt * 16 + ri + (g & 1) * 8;
            int col = kk * 16 + (g >> 1) * 8;
            uint32_t ad = sb + row * ST + col * 2;
            ldsm4(aH[mt], ad);
            ldsm4(aL[mt], ad + SZA);
        }
#pragma unroll
        for (int p = 0; p < 2; p++) {
            int row = wn * 32 + p * 16 + ri + (g >> 1) * 8;
            int col = kk * 16 + (g & 1) * 8;
            uint32_t bd = sb + 2 * SZA + row * ST + col * 2;
            ldsm4(bH[p], bd);
            ldsm4(bL[p], bd + SZB);
        }
#pragma unroll
        for (int mt = 0; mt < 2; mt++)
#pragma unroll
            for (int nt = 0; nt < 4; nt++) {
                int p = nt >> 1, o = (nt & 1) * 2;
                mma_bf16(acc[mt][nt], aH[mt], bH[p][o], bH[p][o + 1]);
                mma_bf16(acc[mt][nt], aH[mt], bL[p][o], bL[p][o + 1]);
                mma_bf16(acc[mt][nt], aL[mt], bH[p][o], bH[p][o + 1]);
            }
    }

    // ---- epilogue: direct global stores with bias ----
#pragma unroll
    for (int mt = 0; mt < 2; mt++) {
#pragma unroll
        for (int nt = 0; nt < 4; nt++) {
            int gr = rowBase + wm * 32 + mt * 16 + (lane >> 2);
            int gc = colBase + wn * 32 + nt * 8 + (lane & 3) * 2;
            float b0 = bias[gc], b1 = bias[gc + 1];
            if (gr < M) {
                float2 o = make_float2(acc[mt][nt][0] + b0, acc[mt][nt][1] + b1);
                *reinterpret_cast<float2*>(&C[(size_t)gr * Ncol + gc]) = o;
            }
            if (gr + 8 < M) {
                float2 o = make_float2(acc[mt][nt][2] + b0, acc[mt][nt][3] + b1);
                *reinterpret_cast<float2*>(&C[(size_t)(gr + 8) * Ncol + gc]) = o;
            }
        }
    }
}

// ---------------- CSR build ----------------------------------------------------
__global__ void k_count(const int* __restrict__ dst, int* cnt) {
    int i = blockIdx.x * blockDim.x + threadIdx.x;
    if (i < EE) atomicAdd(&cnt[dst[i]], 1);
}

__global__ void k_scan(const int* __restrict__ cnt, int* __restrict__ rowptr) {
    __shared__ int wsum[32];
    __shared__ int carry;
    int lane = threadIdx.x & 31, wid = threadIdx.x >> 5;
    if (threadIdx.x == 0) { carry = 0; rowptr[0] = 0; }
    __syncthreads();
    for (int base = 0; base < NN; base += 1024) {
        int i = base + threadIdx.x;
        int v = (i < NN) ? cnt[i] : 0;
        int x = v;
#pragma unroll
        for (int o = 1; o < 32; o <<= 1) {
            int t = __shfl_up_sync(0xffffffffu, x, o);
            if (lane >= o) x += t;
        }
        if (lane == 31) wsum[wid] = x;
        __syncthreads();
        if (wid == 0) {
            int s = wsum[lane];
#pragma unroll
            for (int o = 1; o < 32; o <<= 1) {
                int t = __shfl_up_sync(0xffffffffu, s, o);
                if (lane >= o) s += t;
            }
            wsum[lane] = s;
        }
        __syncthreads();
        int incl = x + (wid ? wsum[wid - 1] : 0) + carry;
        if (i < NN) rowptr[i + 1] = incl;
        int total = wsum[31];
        __syncthreads();
        if (threadIdx.x == 0) carry += total;
        __syncthreads();
    }
}

__global__ void k_scatter(const int* __restrict__ dst, const int* __restrict__ src,
                          const int* __restrict__ rowptr, int* cnt, int* adj) {
    int i = blockIdx.x * blockDim.x + threadIdx.x;
    if (i < EE) {
        int d = dst[i];
        int pos = rowptr[d] + (atomicAdd(&cnt[d], -1) - 1);
        adj[pos] = src[i];
    }
}

// ---------------- fused GATv2 layer (float4 head-group layout) -----------------
__device__ __forceinline__ float head_logit(float4 xv, float4 xr, float4 a) {
    float t = lrelu(xv.x + xr.x) * a.x
            + lrelu(xv.y + xr.y) * a.y
            + lrelu(xv.z + xr.z) * a.z
            + lrelu(xv.w + xr.w) * a.w;
    t += __shfl_xor_sync(0xffffffffu, t, 1);
    t += __shfl_xor_sync(0xffffffffu, t, 2);
    t += __shfl_xor_sync(0xffffffffu, t, 4);
    return t;
}

__global__ __launch_bounds__(256)
void k_aggregate(const float* __restrict__ att, const float* __restrict__ bias) {
    int node = (blockIdx.x * blockDim.x + threadIdx.x) >> 5;
    int lane = threadIdx.x & 31;
    if (node >= NN) return;

    const float4* xli = reinterpret_cast<const float4*>(g_xl + (size_t)node * NHC);
    const float4* xri = reinterpret_cast<const float4*>(g_xr + (size_t)node * NHC);
    const float4* a4  = reinterpret_cast<const float4*>(att);

    float4 attv[3], xrv[3], acc[3];
    float m[3], d[3];
#pragma unroll
    for (int g = 0; g < 3; g++) {
        attv[g] = a4[g * 32 + lane];
        xrv[g]  = xri[g * 32 + lane];
    }
#pragma unroll
    for (int g = 0; g < 3; g++) {
        float4 xv = xli[g * 32 + lane];
        m[g] = head_logit(xv, xrv[g], attv[g]);
        d[g] = 1.f;
        acc[g] = xv;
    }

    const int start = g_rowptr[node], end = g_rowptr[node + 1];
    for (int p = start; p < end; ++p) {
        int s = g_adj[p];
        const float4* xs = reinterpret_cast<const float4*>(g_xl + (size_t)s * NHC);
#pragma unroll
        for (int g = 0; g < 3; g++) {
            float4 xv = xs[g * 32 + lane];
            float t  = head_logit(xv, xrv[g], attv[g]);
            float mn = fmaxf(m[g], t);
            float e  = __expf(fminf(m[g], t) - mn);
            bool  big = t > m[g];
            float pp = big ? e : 1.f;
            float qq = big ? 1.f : e;
            d[g] = d[g] * pp + qq;
            acc[g].x = acc[g].x * pp + qq * xv.x;
            acc[g].y = acc[g].y * pp + qq * xv.y;
            acc[g].z = acc[g].z * pp + qq * xv.z;
            acc[g].w = acc[g].w * pp + qq * xv.w;
            m[g] = mn;
        }
    }

    float4 s4 = make_float4(0.f, 0.f, 0.f, 0.f);
#pragma unroll
    for (int g = 0; g < 3; g++) {
        float dinv = 1.f / d[g];
        s4.x += acc[g].x * dinv;
        s4.y += acc[g].y * dinv;
        s4.z += acc[g].z * dinv;
        s4.w += acc[g].w * dinv;
    }
#pragma unroll
    for (int o = 8; o <= 16; o <<= 1) {
        s4.x += __shfl_xor_sync(0xffffffffu, s4.x, o);
        s4.y += __shfl_xor_sync(0xffffffffu, s4.y, o);
        s4.z += __shfl_xor_sync(0xffffffffu, s4.z, o);
        s4.w += __shfl_xor_sync(0xffffffffu, s4.w, o);
    }
    if (lane < 8) {
        float4 b = reinterpret_cast<const float4*>(bias)[lane];
        float4 o4;
        o4.x = s4.x * (1.f / NH) + b.x;
        o4.y = s4.y * (1.f / NH) + b.y;
        o4.z = s4.z * (1.f / NH) + b.z;
        o4.w = s4.w * (1.f / NH) + b.w;
        o4.x = o4.x > 0.f ? o4.x : (__expf(o4.x) - 1.f);
        o4.y = o4.y > 0.f ? o4.y : (__expf(o4.y) - 1.f);
        o4.z = o4.z > 0.f ? o4.z : (__expf(o4.z) - 1.f);
        o4.w = o4.w > 0.f ? o4.w : (__expf(o4.w) - 1.f);
        reinterpret_cast<float4*>(g_act + (size_t)node * HC)[lane] = o4;
    }
}

// ---------------- output GATv2 layer (heads=1, C=2) ----------------------------
__global__ void k_lin_out(const float* __restrict__ Wl, const float* __restrict__ bl,
                          const float* __restrict__ Wr, const float* __restrict__ br) {
    int node = (blockIdx.x * blockDim.x + threadIdx.x) >> 5;
    int lane = threadIdx.x & 31;
    if (node >= NN) return;
    float hv = g_act[(size_t)node * HC + lane];
#pragma unroll
    for (int j = 0; j < NC; j++) {
        float a = hv * Wl[lane * NC + j];
        float b = hv * Wr[lane * NC + j];
#pragma unroll
        for (int o = 16; o; o >>= 1) {
            a += __shfl_xor_sync(0xffffffffu, a, o);
            b += __shfl_xor_sync(0xffffffffu, b, o);
        }
        if (lane == 0) {
            g_xlo[node * NC + j] = a + bl[j];
            g_xro[node * NC + j] = b + br[j];
        }
    }
}

__global__ void k_out(const float* __restrict__ atto, const float* __restrict__ biaso,
                      float* __restrict__ out) {
    int node = (blockIdx.x * blockDim.x + threadIdx.x) >> 5;
    int lane = threadIdx.x & 31;
    if (node >= NN) return;
    float x0 = g_xlo[2 * node], x1 = g_xlo[2 * node + 1];
    float r0 = g_xro[2 * node], r1 = g_xro[2 * node + 1];
    float a0 = atto[0], a1 = atto[1];
    float sl = a0 * lrelu(x0 + r0) + a1 * lrelu(x1 + r1);

    float m, d, s0, s1;
    if (lane == 0) { m = sl; d = 1.f; s0 = x0; s1 = x1; }
    else           { m = -3.0e38f; d = 0.f; s0 = 0.f; s1 = 0.f; }

    const int start = g_rowptr[node], end = g_rowptr[node + 1];
    for (int p = start + lane; p < end; p += 32) {
        int s = g_adj[p];
        float y0 = g_xlo[2 * s], y1 = g_xlo[2 * s + 1];
        float l  = a0 * lrelu(y0 + r0) + a1 * lrelu(y1 + r1);
        float mn = fmaxf(m, l);
        float sc = __expf(m - mn);
        float w  = __expf(l - mn);
        d  = d * sc + w;
        s0 = s0 * sc + w * y0;
        s1 = s1 * sc + w * y1;
        m  = mn;
    }
#pragma unroll
    for (int o = 16; o; o >>= 1) {
        float m2 = __shfl_xor_sync(0xffffffffu, m, o);
        float d2 = __shfl_xor_sync(0xffffffffu, d, o);
        float t0 = __shfl_xor_sync(0xffffffffu, s0, o);
        float t1 = __shfl_xor_sync(0xffffffffu, s1, o);
        float mn  = fmaxf(m, m2);
        float sc1 = __expf(m - mn);
        float sc2 = __expf(m2 - mn);
        d  = d * sc1 + d2 * sc2;
        s0 = s0 * sc1 + t0 * sc2;
        s1 = s1 * sc1 + t1 * sc2;
        m  = mn;
    }
    if (lane == 0) {
        float dinv = 1.f / d;
        out[2 * node]     = s0 * dinv + biaso[0];
        out[2 * node + 1] = s1 * dinv + biaso[1];
    }
}

// ---------------- launch --------------------------------------------------------
extern "C" void kernel_launch(void* const* d_in, const int* in_sizes, int n_in,
                              void* d_out, int out_size) {
    const float* x     = (const float*)d_in[0];
    const int*   ei    = (const int*)d_in[1];
    const float* Wl0   = (const float*)d_in[2];
    const float* bl0   = (const float*)d_in[3];
    const float* Wr0   = (const float*)d_in[4];
    const float* br0   = (const float*)d_in[5];
    const float* att0  = (const float*)d_in[6];
    const float* bias0 = (const float*)d_in[7];
    const float* Wl1   = (const float*)d_in[8];
    const float* bl1   = (const float*)d_in[9];
    const float* Wr1   = (const float*)d_in[10];
    const float* br1   = (const float*)d_in[11];
    const float* att1  = (const float*)d_in[12];
    const float* bias1 = (const float*)d_in[13];
    const float* Wlo   = (const float*)d_in[14];
    const float* blo   = (const float*)d_in[15];
    const float* Wro   = (const float*)d_in[16];
    const float* bro   = (const float*)d_in[17];
    const float* atto  = (const float*)d_in[18];
    const float* biaso = (const float*)d_in[19];
    float* out = (float*)d_out;

    const int* src = ei;        // edge_index[0]
    const int* dst = ei + EE;   // edge_index[1]

    float *pxl, *pxr, *pact;
    int *pcnt, *prow, *padj;
    cudaGetSymbolAddress((void**)&pxl,  g_xl);
    cudaGetSymbolAddress((void**)&pxr,  g_xr);
    cudaGetSymbolAddress((void**)&pact, g_act);
    cudaGetSymbolAddress((void**)&pcnt, g_cnt);
    cudaGetSymbolAddress((void**)&prow, g_rowptr);
    cudaGetSymbolAddress((void**)&padj, g_adj);

    // dynamic SMEM: full-K hi/lo bf16 tiles
    const int st128 = 128 * 2 + 16, st32 = 32 * 2 + 16;
    const int smem128 = 2 * (128 * st128) + 2 * (64 * st128);  // 104448
    const int smem32  = 2 * (128 * st32)  + 2 * (64 * st32);   // 30720
    cudaFuncSetAttribute(k_gemm_mma<128>, cudaFuncAttributeMaxDynamicSharedMemorySize, smem128);
    cudaFuncSetAttribute(k_gemm_mma<32>,  cudaFuncAttributeMaxDynamicSharedMemorySize, smem32);

    // CSR by destination
    cudaMemsetAsync(pcnt, 0, NN * sizeof(int));
    k_count  <<<(EE + 255) / 256, 256>>>(dst, pcnt);
    k_scan   <<<1, 1024>>>(pcnt, prow);
    k_scatter<<<(EE + 255) / 256, 256>>>(dst, src, prow, pcnt, padj);

    dim3 gg(NHC / 64, (NN + 127) / 128, 2);

    // layer 0: split inputs once, then tensor GEMM
    k_cvtA<128><<<(NN * D0 / 4 + 255) / 256, 256>>>(x, NN);
    k_cvtW<128><<<(2 * NHC * 128 + 255) / 256, 256>>>(Wl0, Wr0);
    k_gemm_mma<128><<<gg, 256, smem128>>>(bl0, pxl, br0, pxr, NN, NHC);
    k_aggregate<<<(NN + 7) / 8, 256>>>(att0, bias0);

    // layer 1
    k_cvtA<32><<<(NN * HC / 4 + 255) / 256, 256>>>(pact, NN);
    k_cvtW<32><<<(2 * NHC * 32 + 255) / 256, 256>>>(Wl1, Wr1);
    k_gemm_mma<32><<<gg, 256, smem32>>>(bl1, pxl, br1, pxr, NN, NHC);
    k_aggregate<<<(NN + 7) / 8, 256>>>(att1, bias1);

    // output layer
    k_lin_out<<<(NN + 7) / 8, 256>>>(Wlo, blo, Wro, bro);
    k_out    <<<(NN + 7) / 8, 256>>>(atto, biaso, out);
}